// round 8
// baseline (speedup 1.0000x reference)
#include <cuda_runtime.h>

// LovaszSoftmax: histogram-based sort-free evaluation.
// B=8, C=21, H=W=512. P = 2,097,152 pixels.
//
// loss_c = sum_i e_i (J_i - J_{i-1}) over pixels sorted by descending error;
// J depends only on (rank, cumulative fg count, total fg). J monotone + tie
// invariance => bucketing errors at width 1/NB gives abs err <= 1/(2NB).
//
// R8: hist kernel is bare REDG-only. R6/R7 showed warp aggregation and
// bucket-0 elision are no-ops on this input (near-uniform softmax spreads
// errors over thousands of buckets) and their MATCH/BALLOT overhead cost
// ~80us. Binding resource is spread-address REDG lane cost (~1.3 cyc/lane
// at L1tex): 44M increments ~= 210us floor for this algorithm.

#define C_ 21
#define HW_ 262144
#define P_ 2097152
#define NB 8192        // error-value buckets
#define NB2 (2 * NB)   // bank 0: background count, bank 1: foreground count
#define NCOPIES 8      // privatized global histogram copies (L2 contention)

__device__ unsigned int g_hist[NCOPIES][C_][NB2];
__device__ unsigned int g_merged[C_][NB2];
__device__ double g_losses[C_];
__device__ int g_lab32;   // 1 if labels are int32, 0 if int64

// ---------------------------------------------------------------------------
__global__ void zero_kernel() {
    unsigned int* h = &g_hist[0][0][0];
    const int total = NCOPIES * C_ * NB2;
    for (int i = blockIdx.x * blockDim.x + threadIdx.x; i < total;
         i += gridDim.x * blockDim.x)
        h[i] = 0u;
}

// Detect label dtype: for int64 (little-endian, values 0..20) all odd int32
// words are zero; for int32 labels they are not (checked over 4096 words).
__global__ void detect_kernel(const int* lab) {
    __shared__ int any;
    if (threadIdx.x == 0) any = 0;
    __syncthreads();
    for (int i = threadIdx.x; i < 2048; i += blockDim.x) {
        if (lab[2 * i + 1] != 0) any = 1;
    }
    __syncthreads();
    if (threadIdx.x == 0) g_lab32 = any;
}

// FFMA-only 2^t for t <= 0 (degree-7 poly on f in [0,1)); avoids MUFU EX2.
__device__ __forceinline__ float fast_exp2(float t) {
    float fi = floorf(t);
    float f = t - fi;
    float p = fmaf(f, 1.5252734e-5f, 1.5403530e-4f);
    p = fmaf(f, p, 1.3333558e-3f);
    p = fmaf(f, p, 9.6181291e-3f);
    p = fmaf(f, p, 5.5504109e-2f);
    p = fmaf(f, p, 2.4022651e-1f);
    p = fmaf(f, p, 6.9314718e-1f);
    p = fmaf(f, p, 1.0f);
    return p * __int_as_float(((int)fi + 127) << 23);
}

// ---------------------------------------------------------------------------
// Fused softmax + error bucketing. One thread per pixel; loads per class are
// fully coalesced. 21 unconditional RED.E.ADD per pixel - no warp voting.
__global__ void __launch_bounds__(256)
hist_kernel(const float* __restrict__ x, const void* __restrict__ labv) {
    int p = blockIdx.x * 256 + threadIdx.x;
    int b = p >> 18;          // batch index (HW_ = 2^18)
    int hw = p & (HW_ - 1);
    const float* base = x + (size_t)b * C_ * HW_ + hw;

    float v[C_];
#pragma unroll
    for (int c = 0; c < C_; c++) v[c] = base[(size_t)c * HW_];

    float m = v[0];
#pragma unroll
    for (int c = 1; c < C_; c++) m = fmaxf(m, v[c]);

    float s = 0.f;
#pragma unroll
    for (int c = 0; c < C_; c++) {
        float t = fmaxf((v[c] - m) * 1.4426950408889634f, -120.f);
        float e2 = fast_exp2(t);
        v[c] = e2;
        s += e2;
    }
    float inv = 1.0f / s;

    int l;
    if (g_lab32) l = ((const int*)labv)[p];
    else         l = (int)(((const long long*)labv)[p]);

    unsigned int* hb = &g_hist[blockIdx.x & (NCOPIES - 1)][0][0];
#pragma unroll
    for (int c = 0; c < C_; c++) {
        float pc = v[c] * inv;
        int isfg = (c == l);
        float e = isfg ? (1.0f - pc) : pc;
        int bkt = (int)(e * (float)NB);
        bkt = min(bkt, NB - 1);
        bkt = max(bkt, 0);
        atomicAdd(hb + c * NB2 + bkt + (isfg ? NB : 0), 1u);  // RED.E.ADD
    }
}

// ---------------------------------------------------------------------------
// Merge privatized copies -> g_merged. Full-chip parallel (measured 6.5us).
__global__ void merge_kernel() {
    int idx = blockIdx.x * 256 + threadIdx.x;   // [0, C_*NB2)
    const unsigned int* h = &g_hist[0][0][0];
    unsigned int s = 0;
#pragma unroll
    for (int k = 0; k < NCOPIES; k++) s += h[k * C_ * NB2 + idx];
    (&g_merged[0][0])[idx] = s;
}

// ---------------------------------------------------------------------------
// Finalize: one block per class over the merged array (1.4MB total).
// Inclusive scan over buckets in DESCENDING error order, then
//   loss_c = sum_b e_hat * (J(incl) - J(excl)),  J(N,F) = N/(N + G - F).
// Packed scan word: fg in high 32 bits, total count in low 32 (<= 2^21).
__global__ void finalize_kernel() {
    extern __shared__ unsigned long long sh[];   // NB entries
    __shared__ unsigned long long tot[256];
    __shared__ double red[256];

    int c = blockIdx.x;
    int tid = threadIdx.x;

    for (int b = tid; b < NB; b += 256) {
        unsigned int bg = g_merged[c][b];
        unsigned int fg = g_merged[c][b + NB];
        sh[NB - 1 - b] =
            ((unsigned long long)fg << 32) | (unsigned long long)(bg + fg);
    }
    __syncthreads();

    // per-thread serial scan of a contiguous chunk
    const int CH = NB / 256;   // 32
    unsigned long long acc = 0ULL;
    int base = tid * CH;
    for (int i = 0; i < CH; i++) {
        acc += sh[base + i];
        sh[base + i] = acc;
    }
    tot[tid] = acc;
    __syncthreads();

    // Hillis-Steele inclusive scan of the 256 thread totals
    for (int off = 1; off < 256; off <<= 1) {
        unsigned long long t = (tid >= off) ? tot[tid - off] : 0ULL;
        __syncthreads();
        tot[tid] += t;
        __syncthreads();
    }
    unsigned long long excl = tot[tid] - acc;
    unsigned long long grand = tot[255];
    double G = (double)(unsigned int)(grand >> 32);

    double lossacc = 0.0;
    unsigned long long prev = excl;
    for (int i = 0; i < CH; i++) {
        unsigned long long cur = sh[base + i] + excl;
        if (cur != prev) {
            unsigned int N1 = (unsigned int)cur;
            unsigned int F1 = (unsigned int)(cur >> 32);
            unsigned int N0 = (unsigned int)prev;
            unsigned int F0 = (unsigned int)(prev >> 32);
            double J1 = N1 ? (double)N1 / ((double)N1 + G - (double)F1) : 0.0;
            double J0 = N0 ? (double)N0 / ((double)N0 + G - (double)F0) : 0.0;
            int bb = NB - 1 - (base + i);
            double eh = ((double)bb + 0.5) / (double)NB;
            lossacc += eh * (J1 - J0);
        }
        prev = cur;
    }

    red[tid] = lossacc;
    __syncthreads();
    for (int off = 128; off > 0; off >>= 1) {
        if (tid < off) red[tid] += red[tid + off];
        __syncthreads();
    }
    if (tid == 0) g_losses[c] = red[0];
}

__global__ void mean_kernel(float* out) {
    if (threadIdx.x == 0 && blockIdx.x == 0) {
        double s = 0.0;
        for (int c = 0; c < C_; c++) s += g_losses[c];
        out[0] = (float)(s / (double)C_);   // LOSS_WEIGHT = 1
    }
}

// ---------------------------------------------------------------------------
extern "C" void kernel_launch(void* const* d_in, const int* in_sizes, int n_in,
                              void* d_out, int out_size) {
    const float* x = (const float*)d_in[0];
    const void* lab = d_in[1];
    float* out = (float*)d_out;

    cudaFuncSetAttribute(finalize_kernel,
                         cudaFuncAttributeMaxDynamicSharedMemorySize, NB * 8);

    zero_kernel<<<2048, 256>>>();
    detect_kernel<<<1, 256>>>((const int*)lab);
    hist_kernel<<<P_ / 256, 256>>>(x, lab);
    merge_kernel<<<(C_ * NB2) / 256, 256>>>();
    finalize_kernel<<<C_, 256, NB * 8>>>();
    mean_kernel<<<1, 32>>>(out);
}

// round 13
// speedup vs baseline: 1.0971x; 1.0971x over previous
#include <cuda_runtime.h>

// LovaszSoftmax: histogram-based sort-free evaluation.
// B=8, C=21, H=W=512. P = 2,097,152 pixels.
//
// loss_c = sum_i e_i (J_i - J_{i-1}) over pixels sorted by descending error;
// J depends only on (rank, cumulative fg count, total fg). J monotone + tie
// invariance => bucketing errors at width 1/NB gives abs err <= 1/(2NB).
//
// Measured config sensitivity (R6/R7/R8): hist cost is 44M spread-address
// REDG; warp aggregation saves ~40us, NCOPIES=32 (vs 8) saves ~40-60us.
// Structural floor ~200us (REDG lane throughput 1.29 cyc/lane).
// Backend (merge + parallel finalize) measured ~20us total.

#define C_ 21
#define HW_ 262144
#define P_ 2097152
#define NB 8192        // error-value buckets
#define NB2 (2 * NB)   // bank 0: background count, bank 1: foreground count
#define NCOPIES 32     // privatized global histogram copies (L2 contention)

__device__ unsigned int g_hist[NCOPIES][C_][NB2];
__device__ unsigned int g_merged[C_][NB2];
__device__ double g_losses[C_];
__device__ int g_lab32;   // 1 if labels are int32, 0 if int64

// ---------------------------------------------------------------------------
__global__ void zero_kernel() {
    unsigned int* h = &g_hist[0][0][0];
    const int total = NCOPIES * C_ * NB2;
    for (int i = blockIdx.x * blockDim.x + threadIdx.x; i < total;
         i += gridDim.x * blockDim.x)
        h[i] = 0u;
}

// Detect label dtype: for int64 (little-endian, values 0..20) all odd int32
// words are zero; for int32 labels they are not (checked over 4096 words).
__global__ void detect_kernel(const int* lab) {
    __shared__ int any;
    if (threadIdx.x == 0) any = 0;
    __syncthreads();
    for (int i = threadIdx.x; i < 2048; i += blockDim.x) {
        if (lab[2 * i + 1] != 0) any = 1;
    }
    __syncthreads();
    if (threadIdx.x == 0) g_lab32 = any;
}

// FFMA-only 2^t for t <= 0 (degree-7 poly on f in [0,1)); avoids MUFU EX2.
__device__ __forceinline__ float fast_exp2(float t) {
    float fi = floorf(t);
    float f = t - fi;
    float p = fmaf(f, 1.5252734e-5f, 1.5403530e-4f);
    p = fmaf(f, p, 1.3333558e-3f);
    p = fmaf(f, p, 9.6181291e-3f);
    p = fmaf(f, p, 5.5504109e-2f);
    p = fmaf(f, p, 2.4022651e-1f);
    p = fmaf(f, p, 6.9314718e-1f);
    p = fmaf(f, p, 1.0f);
    return p * __int_as_float(((int)fi + 127) << 23);
}

// ---------------------------------------------------------------------------
// Fused softmax + error bucketing. One thread per pixel; loads per class are
// fully coalesced. 21 REDs/pixel, warp-aggregated, privatized over 32 copies
// selected per-warp.
__global__ void __launch_bounds__(256)
hist_kernel(const float* __restrict__ x, const void* __restrict__ labv) {
    int p = blockIdx.x * 256 + threadIdx.x;
    int b = p >> 18;          // batch index (HW_ = 2^18)
    int hw = p & (HW_ - 1);
    const float* base = x + (size_t)b * C_ * HW_ + hw;

    float v[C_];
#pragma unroll
    for (int c = 0; c < C_; c++) v[c] = __ldg(base + (size_t)c * HW_);

    float m = v[0];
#pragma unroll
    for (int c = 1; c < C_; c++) m = fmaxf(m, v[c]);

    float s = 0.f;
#pragma unroll
    for (int c = 0; c < C_; c++) {
        float t = fmaxf((v[c] - m) * 1.4426950408889634f, -120.f);
        float e2 = fast_exp2(t);
        v[c] = e2;
        s += e2;
    }
    float inv = 1.0f / s;

    int l;
    if (g_lab32) l = ((const int*)labv)[p];
    else         l = (int)(((const long long*)labv)[p]);

    int lane = threadIdx.x & 31;
    int copy = (blockIdx.x * 8 + (threadIdx.x >> 5)) & (NCOPIES - 1);
    unsigned int* hb = &g_hist[copy][0][0];
#pragma unroll
    for (int c = 0; c < C_; c++) {
        float pc = v[c] * inv;
        int isfg = (c == l);
        float e = isfg ? (1.0f - pc) : pc;
        int bkt = (int)(e * (float)NB);
        bkt = min(bkt, NB - 1);
        bkt = max(bkt, 0);
        int key = bkt | (isfg ? NB : 0);           // [0, NB2)
        unsigned msk = __match_any_sync(0xffffffffu, key);
        if (lane == (__ffs(msk) - 1))              // group leader
            atomicAdd(hb + c * NB2 + key, (unsigned)__popc(msk));
    }
}

// ---------------------------------------------------------------------------
// Merge privatized copies -> g_merged. Full-chip parallel.
__global__ void merge_kernel() {
    int idx = blockIdx.x * 256 + threadIdx.x;   // [0, C_*NB2)
    const unsigned int* h = &g_hist[0][0][0];
    unsigned int s = 0;
#pragma unroll
    for (int k = 0; k < NCOPIES; k++) s += h[k * C_ * NB2 + idx];
    (&g_merged[0][0])[idx] = s;
}

// ---------------------------------------------------------------------------
// Finalize: one block per class over the merged array (1.4MB total).
// Inclusive scan over buckets in DESCENDING error order, then
//   loss_c = sum_b e_hat * (J(incl) - J(excl)),  J(N,F) = N/(N + G - F).
// Packed scan word: fg in high 32 bits, total count in low 32 (<= 2^21).
__global__ void finalize_kernel() {
    extern __shared__ unsigned long long sh[];   // NB entries
    __shared__ unsigned long long tot[256];
    __shared__ double red[256];

    int c = blockIdx.x;
    int tid = threadIdx.x;

    for (int b = tid; b < NB; b += 256) {
        unsigned int bg = g_merged[c][b];
        unsigned int fg = g_merged[c][b + NB];
        sh[NB - 1 - b] =
            ((unsigned long long)fg << 32) | (unsigned long long)(bg + fg);
    }
    __syncthreads();

    // per-thread serial scan of a contiguous chunk
    const int CH = NB / 256;   // 32
    unsigned long long acc = 0ULL;
    int base = tid * CH;
    for (int i = 0; i < CH; i++) {
        acc += sh[base + i];
        sh[base + i] = acc;
    }
    tot[tid] = acc;
    __syncthreads();

    // Hillis-Steele inclusive scan of the 256 thread totals
    for (int off = 1; off < 256; off <<= 1) {
        unsigned long long t = (tid >= off) ? tot[tid - off] : 0ULL;
        __syncthreads();
        tot[tid] += t;
        __syncthreads();
    }
    unsigned long long excl = tot[tid] - acc;
    unsigned long long grand = tot[255];
    double G = (double)(unsigned int)(grand >> 32);

    double lossacc = 0.0;
    unsigned long long prev = excl;
    for (int i = 0; i < CH; i++) {
        unsigned long long cur = sh[base + i] + excl;
        if (cur != prev) {
            unsigned int N1 = (unsigned int)cur;
            unsigned int F1 = (unsigned int)(cur >> 32);
            unsigned int N0 = (unsigned int)prev;
            unsigned int F0 = (unsigned int)(prev >> 32);
            double J1 = N1 ? (double)N1 / ((double)N1 + G - (double)F1) : 0.0;
            double J0 = N0 ? (double)N0 / ((double)N0 + G - (double)F0) : 0.0;
            int bb = NB - 1 - (base + i);
            double eh = ((double)bb + 0.5) / (double)NB;
            lossacc += eh * (J1 - J0);
        }
        prev = cur;
    }

    red[tid] = lossacc;
    __syncthreads();
    for (int off = 128; off > 0; off >>= 1) {
        if (tid < off) red[tid] += red[tid + off];
        __syncthreads();
    }
    if (tid == 0) g_losses[c] = red[0];
}

__global__ void mean_kernel(float* out) {
    if (threadIdx.x == 0 && blockIdx.x == 0) {
        double s = 0.0;
        for (int c = 0; c < C_; c++) s += g_losses[c];
        out[0] = (float)(s / (double)C_);   // LOSS_WEIGHT = 1
    }
}

// ---------------------------------------------------------------------------
extern "C" void kernel_launch(void* const* d_in, const int* in_sizes, int n_in,
                              void* d_out, int out_size) {
    const float* x = (const float*)d_in[0];
    const void* lab = d_in[1];
    float* out = (float*)d_out;

    cudaFuncSetAttribute(finalize_kernel,
                         cudaFuncAttributeMaxDynamicSharedMemorySize, NB * 8);

    zero_kernel<<<4096, 256>>>();
    detect_kernel<<<1, 256>>>((const int*)lab);
    hist_kernel<<<P_ / 256, 256>>>(x, lab);
    merge_kernel<<<(C_ * NB2) / 256, 256>>>();
    finalize_kernel<<<C_, 256, NB * 8>>>();
    mean_kernel<<<1, 32>>>(out);
}

// round 16
// speedup vs baseline: 1.0973x; 1.0002x over previous
#include <cuda_runtime.h>

// LovaszSoftmax: histogram-based sort-free evaluation.
// B=8, C=21, H=W=512. P = 2,097,152 pixels.
//
// loss_c = sum_i e_i (J_i - J_{i-1}) over pixels sorted by descending error;
// J depends only on (rank, cumulative fg count, total fg). J monotone + tie
// invariance => bucketing errors at width 1/NB gives abs err <= 1/(2NB).
//
// Config ledger (measured): warp aggregation -40us; NCOPIES=32 vs 8
// -40..60us; per-WARP copy selection +65us vs per-BLOCK (R13 vs R6) --
// this kernel tests the per-block revert. Backend ~32us measured.

#define C_ 21
#define HW_ 262144
#define P_ 2097152
#define NB 8192        // error-value buckets
#define NB2 (2 * NB)   // bank 0: background count, bank 1: foreground count
#define NCOPIES 32     // privatized global histogram copies

__device__ unsigned int g_hist[NCOPIES][C_][NB2];
__device__ unsigned int g_merged[C_][NB2];
__device__ double g_losses[C_];
__device__ int g_lab32;   // 1 if labels are int32, 0 if int64

// ---------------------------------------------------------------------------
__global__ void zero_kernel() {
    unsigned int* h = &g_hist[0][0][0];
    const int total = NCOPIES * C_ * NB2;
    for (int i = blockIdx.x * blockDim.x + threadIdx.x; i < total;
         i += gridDim.x * blockDim.x)
        h[i] = 0u;
}

// Detect label dtype: for int64 (little-endian, values 0..20) all odd int32
// words are zero; for int32 labels they are not (checked over 4096 words).
__global__ void detect_kernel(const int* lab) {
    __shared__ int any;
    if (threadIdx.x == 0) any = 0;
    __syncthreads();
    for (int i = threadIdx.x; i < 2048; i += blockDim.x) {
        if (lab[2 * i + 1] != 0) any = 1;
    }
    __syncthreads();
    if (threadIdx.x == 0) g_lab32 = any;
}

// FFMA-only 2^t for t <= 0 (degree-7 poly on f in [0,1)); avoids MUFU EX2.
__device__ __forceinline__ float fast_exp2(float t) {
    float fi = floorf(t);
    float f = t - fi;
    float p = fmaf(f, 1.5252734e-5f, 1.5403530e-4f);
    p = fmaf(f, p, 1.3333558e-3f);
    p = fmaf(f, p, 9.6181291e-3f);
    p = fmaf(f, p, 5.5504109e-2f);
    p = fmaf(f, p, 2.4022651e-1f);
    p = fmaf(f, p, 6.9314718e-1f);
    p = fmaf(f, p, 1.0f);
    return p * __int_as_float(((int)fi + 127) << 23);
}

// ---------------------------------------------------------------------------
// Fused softmax + error bucketing. One thread per pixel; loads per class are
// fully coalesced. 21 REDs/pixel, warp-aggregated, privatized over 32 copies
// selected PER-BLOCK.
__global__ void __launch_bounds__(256)
hist_kernel(const float* __restrict__ x, const void* __restrict__ labv) {
    int p = blockIdx.x * 256 + threadIdx.x;
    int b = p >> 18;          // batch index (HW_ = 2^18)
    int hw = p & (HW_ - 1);
    const float* base = x + (size_t)b * C_ * HW_ + hw;

    float v[C_];
#pragma unroll
    for (int c = 0; c < C_; c++) v[c] = __ldg(base + (size_t)c * HW_);

    float m = v[0];
#pragma unroll
    for (int c = 1; c < C_; c++) m = fmaxf(m, v[c]);

    float s = 0.f;
#pragma unroll
    for (int c = 0; c < C_; c++) {
        float t = fmaxf((v[c] - m) * 1.4426950408889634f, -120.f);
        float e2 = fast_exp2(t);
        v[c] = e2;
        s += e2;
    }
    float inv = 1.0f / s;

    int l;
    if (g_lab32) l = ((const int*)labv)[p];
    else         l = (int)(((const long long*)labv)[p]);

    int lane = threadIdx.x & 31;
    unsigned int* hb = &g_hist[blockIdx.x & (NCOPIES - 1)][0][0];
#pragma unroll
    for (int c = 0; c < C_; c++) {
        float pc = v[c] * inv;
        int isfg = (c == l);
        float e = isfg ? (1.0f - pc) : pc;
        int bkt = (int)(e * (float)NB);
        bkt = min(bkt, NB - 1);
        bkt = max(bkt, 0);
        int key = bkt | (isfg ? NB : 0);           // [0, NB2)
        unsigned msk = __match_any_sync(0xffffffffu, key);
        if (lane == (__ffs(msk) - 1))              // group leader
            atomicAdd(hb + c * NB2 + key, (unsigned)__popc(msk));
    }
}

// ---------------------------------------------------------------------------
// Merge privatized copies -> g_merged. Full-chip parallel (measured 11us).
__global__ void merge_kernel() {
    int idx = blockIdx.x * 256 + threadIdx.x;   // [0, C_*NB2)
    const unsigned int* h = &g_hist[0][0][0];
    unsigned int s = 0;
#pragma unroll
    for (int k = 0; k < NCOPIES; k++) s += h[k * C_ * NB2 + idx];
    (&g_merged[0][0])[idx] = s;
}

// ---------------------------------------------------------------------------
// Finalize: one block per class over the merged array (1.4MB total).
// Inclusive scan over buckets in DESCENDING error order, then
//   loss_c = sum_b e_hat * (J(incl) - J(excl)),  J(N,F) = N/(N + G - F).
// Packed scan word: fg in high 32 bits, total count in low 32 (<= 2^21).
__global__ void finalize_kernel() {
    extern __shared__ unsigned long long sh[];   // NB entries
    __shared__ unsigned long long tot[256];
    __shared__ double red[256];

    int c = blockIdx.x;
    int tid = threadIdx.x;

    for (int b = tid; b < NB; b += 256) {
        unsigned int bg = g_merged[c][b];
        unsigned int fg = g_merged[c][b + NB];
        sh[NB - 1 - b] =
            ((unsigned long long)fg << 32) | (unsigned long long)(bg + fg);
    }
    __syncthreads();

    // per-thread serial scan of a contiguous chunk
    const int CH = NB / 256;   // 32
    unsigned long long acc = 0ULL;
    int base = tid * CH;
    for (int i = 0; i < CH; i++) {
        acc += sh[base + i];
        sh[base + i] = acc;
    }
    tot[tid] = acc;
    __syncthreads();

    // Hillis-Steele inclusive scan of the 256 thread totals
    for (int off = 1; off < 256; off <<= 1) {
        unsigned long long t = (tid >= off) ? tot[tid - off] : 0ULL;
        __syncthreads();
        tot[tid] += t;
        __syncthreads();
    }
    unsigned long long excl = tot[tid] - acc;
    unsigned long long grand = tot[255];
    double G = (double)(unsigned int)(grand >> 32);

    double lossacc = 0.0;
    unsigned long long prev = excl;
    for (int i = 0; i < CH; i++) {
        unsigned long long cur = sh[base + i] + excl;
        if (cur != prev) {
            unsigned int N1 = (unsigned int)cur;
            unsigned int F1 = (unsigned int)(cur >> 32);
            unsigned int N0 = (unsigned int)prev;
            unsigned int F0 = (unsigned int)(prev >> 32);
            double J1 = N1 ? (double)N1 / ((double)N1 + G - (double)F1) : 0.0;
            double J0 = N0 ? (double)N0 / ((double)N0 + G - (double)F0) : 0.0;
            int bb = NB - 1 - (base + i);
            double eh = ((double)bb + 0.5) / (double)NB;
            lossacc += eh * (J1 - J0);
        }
        prev = cur;
    }

    red[tid] = lossacc;
    __syncthreads();
    for (int off = 128; off > 0; off >>= 1) {
        if (tid < off) red[tid] += red[tid + off];
        __syncthreads();
    }
    if (tid == 0) g_losses[c] = red[0];
}

__global__ void mean_kernel(float* out) {
    if (threadIdx.x == 0 && blockIdx.x == 0) {
        double s = 0.0;
        for (int c = 0; c < C_; c++) s += g_losses[c];
        out[0] = (float)(s / (double)C_);   // LOSS_WEIGHT = 1
    }
}

// ---------------------------------------------------------------------------
extern "C" void kernel_launch(void* const* d_in, const int* in_sizes, int n_in,
                              void* d_out, int out_size) {
    const float* x = (const float*)d_in[0];
    const void* lab = d_in[1];
    float* out = (float*)d_out;

    cudaFuncSetAttribute(finalize_kernel,
                         cudaFuncAttributeMaxDynamicSharedMemorySize, NB * 8);

    zero_kernel<<<4096, 256>>>();
    detect_kernel<<<1, 256>>>((const int*)lab);
    hist_kernel<<<P_ / 256, 256>>>(x, lab);
    merge_kernel<<<(C_ * NB2) / 256, 256>>>();
    finalize_kernel<<<C_, 256, NB * 8>>>();
    mean_kernel<<<1, 32>>>(out);
}